// round 5
// baseline (speedup 1.0000x reference)
#include <cuda_runtime.h>
#include <math.h>

// ---------------------------------------------------------------------------
// E3GNN, N=512 nodes, fully connected (E=512*511), F=MLP=128, NBLOCKS=2.
//  * First phi_e layer folded into per-node hs/hr precomputes.
//  * One CTA per receiver; segment sums CTA-local.
//  * TILE=128 edges, 8x8 per-thread register tiles, packed fma.rn.f32x2.
//  * Weights streamed via cp.async double-buffered 32-row chunks.
// ---------------------------------------------------------------------------

#define NN    512
#define EPN   511
#define FD    128
#define ASTR  132         // smem activation row stride (floats)
#define TILE  128         // edges per tile
#define NTILE 4           // ceil(511/128)
#define CH    32          // weight chunk rows
#define NCH   4           // chunks per 128x128 GEMM
#define CHF   (CH * FD)   // floats per chunk (4096)

// -------------------- device scratch (no allocs allowed) -------------------
__device__ float g_vec0[NN * 3];
__device__ float g_vec [NN * 3];
__device__ float g_hf  [NN * FD];
__device__ float g_hs  [NN * FD];
__device__ float g_hr  [NN * FD];
__device__ float g_magg[NN * FD];
__device__ float g_vac [NN * 3];
__device__ float g_dummy[32];

// -------------------- helpers ----------------------------------------------
__device__ __forceinline__ float siluf(float x) { return x / (1.f + __expf(-x)); }
__device__ __forceinline__ float sigmf(float x) { return 1.f / (1.f + __expf(-x)); }

__device__ __forceinline__ unsigned long long pack2(float x) {
    unsigned long long r;
    unsigned u = __float_as_uint(x);
    asm("mov.b64 %0, {%1, %1};" : "=l"(r) : "r"(u));
    return r;
}
__device__ __forceinline__ unsigned long long packf2(float lo, float hi) {
    unsigned long long r;
    asm("mov.b64 %0, {%1, %2};" : "=l"(r)
        : "r"(__float_as_uint(lo)), "r"(__float_as_uint(hi)));
    return r;
}
__device__ __forceinline__ float2 unpack2(unsigned long long v) {
    unsigned lo, hi;
    asm("mov.b64 {%0, %1}, %2;" : "=r"(lo), "=r"(hi) : "l"(v));
    return make_float2(__uint_as_float(lo), __uint_as_float(hi));
}
#define FMA2(d, a, b) asm("fma.rn.f32x2 %0, %1, %2, %0;" : "+l"(d) : "l"(a), "l"(b))

__device__ __forceinline__ void cpasync16(unsigned sdst, const void* gsrc) {
    asm volatile("cp.async.cg.shared.global [%0], [%1], 16;\n"
                 :: "r"(sdst), "l"(gsrc));
}
#define CP_COMMIT() asm volatile("cp.async.commit_group;\n" ::: "memory")
#define CP_WAIT0()  asm volatile("cp.async.wait_group 0;\n" ::: "memory")

// -------------------- edge-kernel shared memory -----------------------------
struct __align__(16) ES {
    float Wbuf[2 * CHF];      // double-buffered weight chunk (32 KB)
    float buf0[FD * ASTR];    // activations transposed [k][e]
    float buf1[FD * ASTR];
    float dv [TILE * 3];
    float len[TILE];
    float l2 [TILE];
    float pxs[TILE];
    float gate[TILE];
    float winf[FD];
    float wxo [FD];
    float w0  [FD];
    float hrb [FD];
    float bb1 [FD];
    float bb2 [FD];
    float bbx0[FD];
    float bbx1[FD];
    float maggs[2 * FD];
    float vred[3 * TILE];
    float vaccs[4];
    float rvec[3];
    int   sidx[TILE];
};

// C[e][c] = sum_k A[k][e] * Wg[k][c]  (+bias, opt silu), written transposed
// into Cout[c][e]. 256 threads, each 8 edges x 8 cols. Weight chunks stream
// global -> smem via cp.async, double-buffered; last chunk prefetches Wnext's
// chunk 0 (cross-GEMM pipeline). Ends with a __syncthreads.
template <bool ACT>
__device__ __forceinline__ void gemm_stage(const float* __restrict__ A,
                                           const float* __restrict__ Wg,
                                           const float* __restrict__ Wnext,
                                           const float* __restrict__ bias,
                                           float* __restrict__ Cout,
                                           float* __restrict__ Wbuf, int tid)
{
    const int cc = tid >> 4, ec = tid & 15;     // col group, edge group (8 wide)
    const float* Ap = A + (ec << 3);
    unsigned long long acc[8][4];
#pragma unroll
    for (int i = 0; i < 8; i++)
#pragma unroll
        for (int j = 0; j < 4; j++) acc[i][j] = 0ULL;

    for (int ch = 0; ch < NCH; ch++) {
        // stage next chunk (or next GEMM's chunk 0) via cp.async
        {
            const float* src = (ch < NCH - 1) ? (Wg + (ch + 1) * CHF) : Wnext;
            unsigned sdst = (unsigned)__cvta_generic_to_shared(
                Wbuf + ((ch + 1) & 1) * CHF);
#pragma unroll
            for (int q = 0; q < 4; q++) {
                int u = tid + q * 256;
                cpasync16(sdst + u * 16,
                          reinterpret_cast<const float4*>(src) + u);
            }
            CP_COMMIT();
        }

        // compute current chunk
        const float* Wb = Wbuf + (ch & 1) * CHF + (cc << 3);
        const float* Ac = Ap + (ch * CH) * ASTR;
#pragma unroll 2
        for (int kl = 0; kl < CH; kl++) {
            float4 av0 = *reinterpret_cast<const float4*>(Ac + kl * ASTR);
            float4 av1 = *reinterpret_cast<const float4*>(Ac + kl * ASTR + 4);
            float4 wv0 = *reinterpret_cast<const float4*>(Wb + kl * FD);
            float4 wv1 = *reinterpret_cast<const float4*>(Wb + kl * FD + 4);
            unsigned long long b0 = packf2(wv0.x, wv0.y);
            unsigned long long b1 = packf2(wv0.z, wv0.w);
            unsigned long long b2 = packf2(wv1.x, wv1.y);
            unsigned long long b3 = packf2(wv1.z, wv1.w);
            unsigned long long a0 = pack2(av0.x), a1 = pack2(av0.y),
                               a2 = pack2(av0.z), a3 = pack2(av0.w),
                               a4 = pack2(av1.x), a5 = pack2(av1.y),
                               a6 = pack2(av1.z), a7 = pack2(av1.w);
            FMA2(acc[0][0], a0, b0); FMA2(acc[0][1], a0, b1);
            FMA2(acc[0][2], a0, b2); FMA2(acc[0][3], a0, b3);
            FMA2(acc[1][0], a1, b0); FMA2(acc[1][1], a1, b1);
            FMA2(acc[1][2], a1, b2); FMA2(acc[1][3], a1, b3);
            FMA2(acc[2][0], a2, b0); FMA2(acc[2][1], a2, b1);
            FMA2(acc[2][2], a2, b2); FMA2(acc[2][3], a2, b3);
            FMA2(acc[3][0], a3, b0); FMA2(acc[3][1], a3, b1);
            FMA2(acc[3][2], a3, b2); FMA2(acc[3][3], a3, b3);
            FMA2(acc[4][0], a4, b0); FMA2(acc[4][1], a4, b1);
            FMA2(acc[4][2], a4, b2); FMA2(acc[4][3], a4, b3);
            FMA2(acc[5][0], a5, b0); FMA2(acc[5][1], a5, b1);
            FMA2(acc[5][2], a5, b2); FMA2(acc[5][3], a5, b3);
            FMA2(acc[6][0], a6, b0); FMA2(acc[6][1], a6, b1);
            FMA2(acc[6][2], a6, b2); FMA2(acc[6][3], a6, b3);
            FMA2(acc[7][0], a7, b0); FMA2(acc[7][1], a7, b1);
            FMA2(acc[7][2], a7, b2); FMA2(acc[7][3], a7, b3);
        }

        if (ch < NCH - 1) {
            CP_WAIT0();
            __syncthreads();
        }
    }

    // epilogue: bias (+silu), transposed store
#pragma unroll
    for (int i = 0; i < 8; i++) {
        int e = (ec << 3) + i;
#pragma unroll
        for (int j = 0; j < 4; j++) {
            float2 v = unpack2(acc[i][j]);
            int c = (cc << 3) + (j << 1);
            float r0 = v.x + bias[c];
            float r1 = v.y + bias[c + 1];
            if (ACT) { r0 = siluf(r0); r1 = siluf(r1); }
            Cout[c * ASTR + e]       = r0;
            Cout[(c + 1) * ASTR + e] = r1;
        }
    }
    CP_WAIT0();
    __syncthreads();
}

// -------------------- edge kernel: one CTA per receiver ---------------------
__global__ void __launch_bounds__(256, 1)
kedge(const int* __restrict__ senders,
      const float* __restrict__ We0r0,
      const float* __restrict__ We1, const float* __restrict__ be1,
      const float* __restrict__ We2, const float* __restrict__ be2,
      const float* __restrict__ Winf, const float* __restrict__ binfp,
      const float* __restrict__ Wx0, const float* __restrict__ bx0,
      const float* __restrict__ Wx1, const float* __restrict__ bx1,
      const float* __restrict__ Wxo, const float* __restrict__ bxop)
{
    extern __shared__ char smraw[];
    ES* S = reinterpret_cast<ES*>(smraw);
    const int t = threadIdx.x;
    const int i = blockIdx.x;

    if (t < FD) {
        S->winf[t] = Winf[t];
        S->wxo[t]  = Wxo[t];
        S->w0[t]   = We0r0[t];
        S->hrb[t]  = g_hr[i * FD + t];
        S->bb1[t]  = be1[t];
        S->bb2[t]  = be2[t];
        S->bbx0[t] = bx0[t];
        S->bbx1[t] = bx1[t];
    }
    if (t < 4) S->vaccs[t] = 0.f;
    if (t < 3) S->rvec[t] = g_vec[i * 3 + t];
    const float binf_s = binfp[0];
    const float bxo_s  = bxop[0];

    // prologue: stage We1 chunk 0 into Wbuf[0]
    {
        unsigned sdst = (unsigned)__cvta_generic_to_shared(S->Wbuf);
#pragma unroll
        for (int q = 0; q < 4; q++) {
            int u = t + q * 256;
            cpasync16(sdst + u * 16, reinterpret_cast<const float4*>(We1) + u);
        }
        CP_COMMIT();
        CP_WAIT0();
    }

    const int kk = t & 127;        // feature index
    const int hh = t >> 7;         // edge half (0/1)
    float mreg = 0.f;              // magg partial for (hh, kk)

    __syncthreads();

    for (int tile = 0; tile < NTILE; tile++) {
        // ---- stage 1: senders, dv, len, l2 -----------------------------
        if (t < TILE) {
            int je = tile * TILE + t;
            bool valid = je < EPN;
            int s = valid ? senders[i * EPN + je] : i;
            S->sidx[t] = s;
            float d0 = 0.f, d1 = 0.f, d2 = 0.f;
            if (valid) {
                d0 = S->rvec[0] - g_vec[s * 3 + 0];
                d1 = S->rvec[1] - g_vec[s * 3 + 1];
                d2 = S->rvec[2] - g_vec[s * 3 + 2];
            }
            S->dv[t * 3 + 0] = d0;
            S->dv[t * 3 + 1] = d1;
            S->dv[t * 3 + 2] = d2;
            float dot = d0 * d0 + d1 * d1 + d2 * d2 + 1e-20f;
            S->l2[t]  = valid ? dot : 0.f;
            S->len[t] = sqrtf(dot);
        }
        __syncthreads();

        // ---- stage 2: act0[k][e] = silu(l2*w0[k] + hs[s][k] + hr[i][k]) -
        {
            float w0v = S->w0[kk];
            float hrv = S->hrb[kk];
            float* dst = S->buf0 + kk * ASTR + hh * 64;
            const int* sp = S->sidx + hh * 64;
            const float* l2p = S->l2 + hh * 64;
#pragma unroll 4
            for (int e = 0; e < 64; e++) {
                int s = sp[e];
                float v = l2p[e] * w0v + g_hs[s * FD + kk] + hrv;
                dst[e] = siluf(v);
            }
        }
        __syncthreads();

        // ---- GEMM1: buf1 = silu(buf0 @ We1 + be1) ----------------------
        gemm_stage<true >(S->buf0, We1, We2, S->bb1, S->buf1, S->Wbuf, t);
        // ---- GEMM2: buf0 = buf1 @ We2 + be2   (m) ----------------------
        gemm_stage<false>(S->buf1, We2, Wx0, S->bb2, S->buf0, S->Wbuf, t);

        // ---- gate[e] = sigmoid(m . winf + binf), split-k pairs ---------
        {
            int e = t >> 1, kh = t & 1;
            const float* col = S->buf0 + e + (kh * 64) * ASTR;
            const float* wv  = S->winf + kh * 64;
            float a0 = 0.f, a1 = 0.f;
#pragma unroll 8
            for (int k = 0; k < 64; k += 2) {
                a0 += col[k * ASTR] * wv[k];
                a1 += col[(k + 1) * ASTR] * wv[k + 1];
            }
            float acc = a0 + a1;
            float other = __shfl_xor_sync(0xffffffffu, acc, 1);
            if (kh == 0) {
                bool valid = (tile * TILE + e) < EPN;
                S->gate[e] = valid ? sigmf(binf_s + acc + other) : 0.f;
            }
        }
        __syncthreads();

        // ---- magg partial ----------------------------------------------
        {
            const float* row = S->buf0 + kk * ASTR + hh * 64;
            const float* gt  = S->gate + hh * 64;
            float p0 = 0.f, p1 = 0.f;
#pragma unroll
            for (int e = 0; e < 64; e += 4) {
                float4 r = *reinterpret_cast<const float4*>(row + e);
                float4 g = *reinterpret_cast<const float4*>(gt + e);
                p0 += r.x * g.x + r.y * g.y;
                p1 += r.z * g.z + r.w * g.w;
            }
            mreg += p0 + p1;
        }

        // ---- GEMM3: buf1 = silu(buf0 @ Wx0 + bx0) ----------------------
        gemm_stage<true>(S->buf0, Wx0, Wx1, S->bbx0, S->buf1, S->Wbuf, t);
        // ---- GEMM4: buf0 = silu(buf1 @ Wx1 + bx1) ----------------------
        gemm_stage<true>(S->buf1, Wx1, We1, S->bbx1, S->buf0, S->Wbuf, t);

        // ---- px[e] = B1 . wxo + bxo; pxs = px/(1+len) ------------------
        {
            int e = t >> 1, kh = t & 1;
            const float* col = S->buf0 + e + (kh * 64) * ASTR;
            const float* wv  = S->wxo + kh * 64;
            float a0 = 0.f, a1 = 0.f;
#pragma unroll 8
            for (int k = 0; k < 64; k += 2) {
                a0 += col[k * ASTR] * wv[k];
                a1 += col[(k + 1) * ASTR] * wv[k + 1];
            }
            float acc = a0 + a1;
            float other = __shfl_xor_sync(0xffffffffu, acc, 1);
            if (kh == 0)
                S->pxs[e] = (bxo_s + acc + other) / (1.f + S->len[e]);
        }
        __syncthreads();

        // ---- vac partial (warp-parallel) -------------------------------
        if (t < TILE) {
            float p = S->pxs[t];
            S->vred[0 * TILE + t] = p * S->dv[t * 3 + 0];
            S->vred[1 * TILE + t] = p * S->dv[t * 3 + 1];
            S->vred[2 * TILE + t] = p * S->dv[t * 3 + 2];
        }
        __syncthreads();
        if (t < 96) {
            int c = t >> 5, l = t & 31;
            const float* vr = S->vred + c * TILE;
            float v = (vr[l] + vr[l + 32]) + (vr[l + 64] + vr[l + 96]);
#pragma unroll
            for (int o = 16; o; o >>= 1) v += __shfl_down_sync(0xffffffffu, v, o);
            if (l == 0) S->vaccs[c] += v;
        }
        __syncthreads();
    }

    // ---- writeout -------------------------------------------------------
    S->maggs[t] = mreg;
    __syncthreads();
    if (t < FD)
        g_magg[i * FD + t] = (S->maggs[t] + S->maggs[FD + t]) * rsqrtf(511.f);
    if (t < 3)
        g_vac[i * 3 + t] = S->vaccs[t] * (1.f / 511.f);
}

// -------------------- setup: center coordinates -----------------------------
__global__ void ksetup(const float* __restrict__ x)
{
    __shared__ float r0[256], r1[256], r2[256];
    __shared__ float mean[3];
    int t = threadIdx.x;
    float s0 = 0.f, s1 = 0.f, s2 = 0.f;
    for (int n = t; n < NN; n += 256) {
        s0 += x[n * 3 + 0]; s1 += x[n * 3 + 1]; s2 += x[n * 3 + 2];
    }
    r0[t] = s0; r1[t] = s1; r2[t] = s2;
    __syncthreads();
    for (int s = 128; s > 0; s >>= 1) {
        if (t < s) { r0[t] += r0[t + s]; r1[t] += r1[t + s]; r2[t] += r2[t + s]; }
        __syncthreads();
    }
    if (t == 0) {
        mean[0] = r0[0] * (1.f / NN);
        mean[1] = r1[0] * (1.f / NN);
        mean[2] = r2[0] * (1.f / NN);
    }
    __syncthreads();
    for (int n = t; n < NN; n += 256) {
#pragma unroll
        for (int c = 0; c < 3; c++) {
            float v = x[n * 3 + c] - mean[c];
            g_vec[n * 3 + c]  = v;
            g_vec0[n * 3 + c] = v;
        }
    }
}

// -------------------- dummy (shifts ncu -s 5 capture onto kedge) ------------
__global__ void kdummy() { g_dummy[threadIdx.x] = 0.f; }

// -------------------- node init: hf, hs, hr (block 0) -----------------------
__global__ void __launch_bounds__(256) knode0(
    const float* __restrict__ h,
    const float* __restrict__ Wh0, const float* __restrict__ bh0,
    const float* __restrict__ We0, const float* __restrict__ be0)
{
    __shared__ float hrow[16];
    __shared__ float hfs[FD];
    __shared__ float part[256];
    int i = blockIdx.x, t = threadIdx.x;
    int c = t & 127, hh = t >> 7;
    if (t < 16) hrow[t] = h[i * 16 + t];
    __syncthreads();
    if (t < FD) {
        float acc = bh0[t];
#pragma unroll
        for (int k = 0; k < 16; k++) acc += hrow[k] * Wh0[k * FD + t];
        g_hf[i * FD + t] = acc;
        hfs[t] = acc;
    }
    __syncthreads();
    {
        float a0 = 0.f, a1 = 0.f, b0 = 0.f, b1 = 0.f;
        const float* W1 = We0 + (1 + hh * 64) * FD;
        const float* W2 = We0 + (129 + hh * 64) * FD;
        const float* xv = hfs + hh * 64;
#pragma unroll 4
        for (int k = 0; k < 64; k += 2) {
            a0 += xv[k] * W1[k * FD + c];       a1 += xv[k + 1] * W1[(k + 1) * FD + c];
            b0 += xv[k] * W2[k * FD + c];       b1 += xv[k + 1] * W2[(k + 1) * FD + c];
        }
        part[t] = a0 + a1;
        __syncthreads();
        if (t < FD) g_hs[i * FD + t] = part[t] + part[t + FD];
        __syncthreads();
        part[t] = b0 + b1;
        __syncthreads();
        if (t < FD) g_hr[i * FD + t] = part[t] + part[t + FD] + be0[t];
    }
}

// -------------------- node update (phi_h) + next-block hs/hr ----------------
__global__ void __launch_bounds__(256) knode(
    const float* __restrict__ Wp0, const float* __restrict__ bp0,
    const float* __restrict__ Wp1, const float* __restrict__ bp1,
    const float* __restrict__ Wpl, const float* __restrict__ bpl,
    const float* __restrict__ We0n, const float* __restrict__ be0n,
    int doNext)
{
    __shared__ float in0[2 * FD];
    __shared__ float t0s[FD];
    __shared__ float t1s[FD];
    __shared__ float nhfs[FD];
    __shared__ float part[256];
    int i = blockIdx.x, t = threadIdx.x;
    int c = t & 127, hh = t >> 7;

    if (t < 3) g_vec[i * 3 + t] += g_vac[i * 3 + t];
    if (t < FD) in0[t] = g_magg[i * FD + t];
    else        in0[t] = g_hf[i * FD + (t - FD)];
    __syncthreads();

    // Wp0: 256 x 128, split k over two halves
    {
        float a0 = 0.f, a1 = 0.f, a2 = 0.f, a3 = 0.f;
        const float* W  = Wp0 + hh * FD * FD;
        const float* xv = in0 + hh * FD;
#pragma unroll 4
        for (int k = 0; k < FD; k += 4) {
            a0 += xv[k]     * W[(k    ) * FD + c];
            a1 += xv[k + 1] * W[(k + 1) * FD + c];
            a2 += xv[k + 2] * W[(k + 2) * FD + c];
            a3 += xv[k + 3] * W[(k + 3) * FD + c];
        }
        part[t] = (a0 + a1) + (a2 + a3);
    }
    __syncthreads();
    if (t < FD) t0s[t] = siluf(part[t] + part[t + FD] + bp0[t]);
    __syncthreads();

    // Wp1: 128 x 128
    {
        float a0 = 0.f, a1 = 0.f, a2 = 0.f, a3 = 0.f;
        const float* W  = Wp1 + hh * 64 * FD;
        const float* xv = t0s + hh * 64;
#pragma unroll 4
        for (int k = 0; k < 64; k += 4) {
            a0 += xv[k]     * W[(k    ) * FD + c];
            a1 += xv[k + 1] * W[(k + 1) * FD + c];
            a2 += xv[k + 2] * W[(k + 2) * FD + c];
            a3 += xv[k + 3] * W[(k + 3) * FD + c];
        }
        part[t] = (a0 + a1) + (a2 + a3);
    }
    __syncthreads();
    if (t < FD) t1s[t] = part[t] + part[t + FD] + bp1[t];
    __syncthreads();

    // Wpl: 128 x 128
    {
        float a0 = 0.f, a1 = 0.f, a2 = 0.f, a3 = 0.f;
        const float* W  = Wpl + hh * 64 * FD;
        const float* xv = t1s + hh * 64;
#pragma unroll 4
        for (int k = 0; k < 64; k += 4) {
            a0 += xv[k]     * W[(k    ) * FD + c];
            a1 += xv[k + 1] * W[(k + 1) * FD + c];
            a2 += xv[k + 2] * W[(k + 2) * FD + c];
            a3 += xv[k + 3] * W[(k + 3) * FD + c];
        }
        part[t] = (a0 + a1) + (a2 + a3);
    }
    __syncthreads();
    if (t < FD) {
        float nhf = g_hf[i * FD + t] + part[t] + part[t + FD] + bpl[t];
        g_hf[i * FD + t] = nhf;
        nhfs[t] = nhf;
    }
    __syncthreads();

    if (doNext) {
        float a0 = 0.f, a1 = 0.f, b0 = 0.f, b1 = 0.f;
        const float* W1 = We0n + (1 + hh * 64) * FD;
        const float* W2 = We0n + (129 + hh * 64) * FD;
        const float* xv = nhfs + hh * 64;
#pragma unroll 4
        for (int k = 0; k < 64; k += 2) {
            a0 += xv[k] * W1[k * FD + c];       a1 += xv[k + 1] * W1[(k + 1) * FD + c];
            b0 += xv[k] * W2[k * FD + c];       b1 += xv[k + 1] * W2[(k + 1) * FD + c];
        }
        part[t] = a0 + a1;
        __syncthreads();
        if (t < FD) g_hs[i * FD + t] = part[t] + part[t + FD];
        __syncthreads();
        part[t] = b0 + b1;
        __syncthreads();
        if (t < FD) g_hr[i * FD + t] = part[t] + part[t + FD] + be0n[t];
    }
}

// -------------------- readout -----------------------------------------------
__global__ void kout(const float* __restrict__ Wv,
                     const float* __restrict__ Wr, const float* __restrict__ br,
                     float* __restrict__ out)
{
    __shared__ float red[FD];
    __shared__ float p[FD];
    int i = blockIdx.x, c = threadIdx.x;
    float hf = g_hf[i * FD + c];

    red[c] = hf;
    __syncthreads();
    for (int s = 64; s > 0; s >>= 1) {
        if (c < s) red[c] = fmaxf(red[c], red[c + s]);
        __syncthreads();
    }
    float mx = red[0];
    __syncthreads();
    float ex = __expf(hf - mx);
    red[c] = ex;
    __syncthreads();
    for (int s = 64; s > 0; s >>= 1) {
        if (c < s) red[c] += red[c + s];
        __syncthreads();
    }
    float inv = 1.f / red[0];
    __syncthreads();
    p[c] = ex * inv;
    __syncthreads();

    if (c < 32) {
        float a = br[c];
#pragma unroll 8
        for (int k = 0; k < FD; k++) a += p[k] * Wr[k * 32 + c];
        out[NN * 6 + i * 32 + c] = a;
    }
    if (c < 6) {
        int o = c / 3, cc = c % 3;
        out[i * 6 + c] = (g_vec[i * 3 + cc] - g_vec0[i * 3 + cc]) * Wv[o];
    }
}

// -------------------- host launch -------------------------------------------
extern "C" void kernel_launch(void* const* d_in, const int* in_sizes, int n_in,
                              void* d_out, int out_size)
{
    const float* x   = (const float*)d_in[0];
    const float* h   = (const float*)d_in[1];
    const int* snd   = (const int*)  d_in[2];
    const float* Wh0 = (const float*)d_in[4];
    const float* bh0 = (const float*)d_in[5];
    const float* We0 = (const float*)d_in[6];
    const float* be0 = (const float*)d_in[7];
    const float* We1 = (const float*)d_in[8];
    const float* be1 = (const float*)d_in[9];
    const float* We2 = (const float*)d_in[10];
    const float* be2 = (const float*)d_in[11];
    const float* Winf= (const float*)d_in[12];
    const float* binf= (const float*)d_in[13];
    const float* Wx0 = (const float*)d_in[14];
    const float* bx0 = (const float*)d_in[15];
    const float* Wx1 = (const float*)d_in[16];
    const float* bx1 = (const float*)d_in[17];
    const float* Wxo = (const float*)d_in[18];
    const float* bxo = (const float*)d_in[19];
    const float* Wp0 = (const float*)d_in[20];
    const float* bp0 = (const float*)d_in[21];
    const float* Wp1 = (const float*)d_in[22];
    const float* bp1 = (const float*)d_in[23];
    const float* Wpl = (const float*)d_in[24];
    const float* bpl = (const float*)d_in[25];
    const float* Wv  = (const float*)d_in[26];
    const float* Wr  = (const float*)d_in[27];
    const float* br  = (const float*)d_in[28];
    float* out = (float*)d_out;

    int smem = (int)sizeof(ES);
    cudaFuncSetAttribute(kedge, cudaFuncAttributeMaxDynamicSharedMemorySize, smem);

    const int WB  = FD * FD;     // 128*128 per-block weight stride
    const int W0B = 257 * FD;    // We0 per-block stride
    const int WP0 = 2 * FD * FD; // Wp0 per-block stride

    ksetup<<<1, 256>>>(x);
    knode0<<<NN, 256>>>(h, Wh0, bh0, We0, be0);
    kdummy<<<1, 32>>>();   // shifts ncu -s 5 capture onto the 2nd kedge

    for (int b = 0; b < 2; b++) {
        kedge<<<NN, 256, smem>>>(snd,
            We0 + b * W0B,
            We1 + b * WB, be1 + b * FD,
            We2 + b * WB, be2 + b * FD,
            Winf + b * FD, binf + b,
            Wx0 + b * WB, bx0 + b * FD,
            Wx1 + b * WB, bx1 + b * FD,
            Wxo + b * FD, bxo + b);
        knode<<<NN, 256>>>(Wp0 + b * WP0, bp0 + b * FD,
                           Wp1 + b * WB,  bp1 + b * FD,
                           Wpl + b * WB,  bpl + b * FD,
                           We0 + W0B, be0 + FD, b == 0 ? 1 : 0);
    }

    kout<<<NN, FD>>>(Wv, Wr, br, out);
}

// round 8
// speedup vs baseline: 1.4835x; 1.4835x over previous
#include <cuda_runtime.h>
#include <cuda_bf16.h>
#include <math.h>

#define NN    512
#define EPN   511
#define FD    128
#define TILE  128
#define NTILE 4

__device__ float g_vec0[NN * 3];
__device__ float g_vec [NN * 3];
__device__ float g_hf  [NN * FD];
__device__ float g_hs  [NN * FD];
__device__ float g_hr  [NN * FD];
__device__ float g_magg[NN * FD];
__device__ float g_vac [NN * 3];
// 8 matrices (2 blocks x {We1,We2,Wx0,Wx1}) as T[n][k] images, 64KB each: [hi|lo]
__device__ __align__(16) __nv_bfloat16 g_wb[8 * 32768];

__device__ __forceinline__ float siluf(float x) { return x / (1.f + __expf(-x)); }
__device__ __forceinline__ float sigmf(float x) { return 1.f / (1.f + __expf(-x)); }

__device__ __forceinline__ unsigned smem_u32(const void* p) {
    unsigned a;
    asm("{ .reg .u64 t; cvta.to.shared.u64 t, %1; cvt.u32.u64 %0, t; }" : "=r"(a) : "l"(p));
    return a;
}
__device__ __forceinline__ void cpasync16(unsigned d, const void* g) {
    asm volatile("cp.async.cg.shared.global [%0], [%1], 16;" :: "r"(d), "l"(g));
}
#define CP_COMMIT() asm volatile("cp.async.commit_group;" ::: "memory")
#define CP_WAIT0()  asm volatile("cp.async.wait_group 0;"  ::: "memory")

__device__ __forceinline__ void ldsm4(unsigned* r, unsigned a) {
    asm volatile("ldmatrix.sync.aligned.m8n8.x4.shared.b16 {%0,%1,%2,%3}, [%4];"
        : "=r"(r[0]), "=r"(r[1]), "=r"(r[2]), "=r"(r[3]) : "r"(a));
}
__device__ __forceinline__ void mma16816(float* c, const unsigned* a,
                                         unsigned b0, unsigned b1) {
    asm volatile("mma.sync.aligned.m16n8k16.row.col.f32.bf16.bf16.f32 "
        "{%0,%1,%2,%3}, {%4,%5,%6,%7}, {%8,%9}, {%0,%1,%2,%3};"
        : "+f"(c[0]), "+f"(c[1]), "+f"(c[2]), "+f"(c[3])
        : "r"(a[0]), "r"(a[1]), "r"(a[2]), "r"(a[3]), "r"(b0), "r"(b1));
}

// image layout: row-major [row][k], 256B rows, 16B chunks XOR-swizzled by row&7
__device__ __forceinline__ int img_off(int e, int c) {
    return (e << 8) + ((((c >> 3) ^ (e & 7))) << 4) + ((c & 7) << 1);
}
__device__ __forceinline__ void st_split2(char* hb, char* lb, int off,
                                          float v0, float v1) {
    __nv_bfloat16 h0 = __float2bfloat16(v0), h1 = __float2bfloat16(v1);
    __nv_bfloat16 l0 = __float2bfloat16(v0 - __bfloat162float(h0));
    __nv_bfloat16 l1 = __float2bfloat16(v1 - __bfloat162float(h1));
    *reinterpret_cast<unsigned*>(hb + off) =
        (unsigned)__bfloat16_as_ushort(h0) | ((unsigned)__bfloat16_as_ushort(h1) << 16);
    *reinterpret_cast<unsigned*>(lb + off) =
        (unsigned)__bfloat16_as_ushort(l0) | ((unsigned)__bfloat16_as_ushort(l1) << 16);
}

struct __align__(16) ES {
    char xhi[32768]; char xlo[32768];   // act0 / m images [e][k]
    char yhi[32768]; char ylo[32768];   // GEMM1/3 output images
    char bbuf[65536];                   // current weight pair {hi|lo}, T[n][k]
    float dv[3 * TILE], len[TILE], l2[TILE], gate[TILE], pxs[TILE];
    float gpart[2 * TILE];
    float w0[FD], hrb[FD], winf[FD], wxo[FD];
    float bb1[FD], bb2[FD], bbx0[FD], bbx1[FD];
    float maggs[2 * FD], vred[3 * TILE], vaccs[4], rvec[3];
    int   sidx[TILE];
};

__device__ __forceinline__ void loadB(char* dst, const __nv_bfloat16* blob, int t) {
    unsigned sd = smem_u32(dst);
    const float4* src = reinterpret_cast<const float4*>(blob);
#pragma unroll
    for (int q = 0; q < 16; q++) { int u = t + q * 256; cpasync16(sd + u * 16, src + u); }
    CP_COMMIT();
}

// C[128e][128c] = split3( A @ W ); epilogue: +bias (opt silu / dot / store split).
// Internally: mma loops -> syncthreads -> cp.async next weight blob -> epilogue.
template <bool ACT, bool DOT, bool STORE>
__device__ __forceinline__ void gemm_tc(ES* S, const char* Ahi, const char* Alo,
                                        const __nv_bfloat16* nextblob,
                                        const float* bias, const float* dw,
                                        char* Ohi, char* Olo, int t)
{
    const int w = t >> 5, lane = t & 31;
    const int e0 = (w >> 1) * 32, c0 = (w & 1) * 64;
    const unsigned l7 = lane & 7;
    float acc[2][8][4];
#pragma unroll
    for (int mt = 0; mt < 2; mt++)
#pragma unroll
        for (int nt = 0; nt < 8; nt++)
#pragma unroll
            for (int q = 0; q < 4; q++) acc[mt][nt][q] = 0.f;

    const unsigned arow = e0 + (lane & 15);
    const unsigned acb  = lane >> 4;
    const unsigned brow = c0 + ((lane >> 4) << 3) + l7;
    const unsigned bcb  = (lane >> 3) & 1;

#pragma unroll
    for (int term = 0; term < 3; term++) {
        const char* As = (term == 2) ? Alo : Ahi;
        const char* Bs = S->bbuf + ((term == 1) ? 32768 : 0);
        unsigned ab = smem_u32(As) + arow * 256;
        unsigned bb = smem_u32(Bs) + brow * 256;
#pragma unroll
        for (int ks = 0; ks < 8; ks++) {
            unsigned a0[4], a1[4];
            unsigned ach = (((unsigned)(ks << 1)) | acb) ^ l7;
            ldsm4(a0, ab + (ach << 4));
            ldsm4(a1, ab + 16 * 256 + (ach << 4));
            unsigned bch = (((unsigned)(ks << 1)) | bcb) ^ l7;
#pragma unroll
            for (int p = 0; p < 4; p++) {
                unsigned b[4];
                ldsm4(b, bb + p * 16 * 256 + (bch << 4));
                mma16816(acc[0][2 * p],     a0, b[0], b[1]);
                mma16816(acc[0][2 * p + 1], a0, b[2], b[3]);
                mma16816(acc[1][2 * p],     a1, b[0], b[1]);
                mma16816(acc[1][2 * p + 1], a1, b[2], b[3]);
            }
        }
    }
    __syncthreads();                 // all warps done reading bbuf + A images
    loadB(S->bbuf, nextblob, t);     // stream next weights under the epilogue

    const int r = lane >> 2, n2 = (lane & 3) * 2;
    float drow[2][2] = {{0.f, 0.f}, {0.f, 0.f}};
#pragma unroll
    for (int mt = 0; mt < 2; mt++) {
        int eA = e0 + mt * 16 + r;
#pragma unroll
        for (int nt = 0; nt < 8; nt++) {
            int c = c0 + nt * 8 + n2;
            float b0v = bias[c], b1v = bias[c + 1];
            float v00 = acc[mt][nt][0] + b0v, v01 = acc[mt][nt][1] + b1v;
            float v10 = acc[mt][nt][2] + b0v, v11 = acc[mt][nt][3] + b1v;
            if (ACT) { v00 = siluf(v00); v01 = siluf(v01);
                       v10 = siluf(v10); v11 = siluf(v11); }
            if (DOT) {
                drow[mt][0] += v00 * dw[c] + v01 * dw[c + 1];
                drow[mt][1] += v10 * dw[c] + v11 * dw[c + 1];
            }
            if (STORE) {
                st_split2(Ohi, Olo, img_off(eA, c), v00, v01);
                st_split2(Ohi, Olo, img_off(eA + 8, c), v10, v11);
            }
        }
    }
    if (DOT) {
#pragma unroll
        for (int mt = 0; mt < 2; mt++)
#pragma unroll
            for (int hb = 0; hb < 2; hb++) {
                float v = drow[mt][hb];
                v += __shfl_xor_sync(0xffffffffu, v, 1);
                v += __shfl_xor_sync(0xffffffffu, v, 2);
                if ((lane & 3) == 0)
                    S->gpart[(w & 1) * TILE + e0 + mt * 16 + hb * 8 + r] = v;
            }
    }
}

__global__ void __launch_bounds__(256, 1)
kedge(const int* __restrict__ senders, const float* __restrict__ We0r0,
      const float* __restrict__ be1, const float* __restrict__ be2,
      const float* __restrict__ Winf, const float* __restrict__ binfp,
      const float* __restrict__ bx0, const float* __restrict__ bx1,
      const float* __restrict__ Wxo, const float* __restrict__ bxop, int blk)
{
    extern __shared__ char smraw[];
    ES* S = reinterpret_cast<ES*>(smraw);
    const int t = threadIdx.x, i = blockIdx.x;
    const __nv_bfloat16* wb = g_wb + blk * 4 * 32768;

    if (t < FD) {
        S->w0[t] = We0r0[t]; S->hrb[t] = g_hr[i * FD + t];
        S->winf[t] = Winf[t]; S->wxo[t] = Wxo[t];
        S->bb1[t] = be1[t]; S->bb2[t] = be2[t];
        S->bbx0[t] = bx0[t]; S->bbx1[t] = bx1[t];
    }
    if (t < 4) S->vaccs[t] = 0.f;
    if (t < 3) S->rvec[t] = g_vec[i * 3 + t];
    const float binf_s = binfp[0], bxo_s = bxop[0];

    loadB(S->bbuf, wb, t);          // We1
    __syncthreads();

    const int kk = t & 127, hh = t >> 7;
    float mreg = 0.f;

    for (int tile = 0; tile < NTILE; tile++) {
        if (t < TILE) {                                  // stage 1
            int je = tile * TILE + t;
            bool valid = je < EPN;
            int s = valid ? senders[i * EPN + je] : i;
            S->sidx[t] = s;
            float d0 = 0.f, d1 = 0.f, d2 = 0.f;
            if (valid) {
                d0 = S->rvec[0] - g_vec[s * 3 + 0];
                d1 = S->rvec[1] - g_vec[s * 3 + 1];
                d2 = S->rvec[2] - g_vec[s * 3 + 2];
            }
            S->dv[t * 3] = d0; S->dv[t * 3 + 1] = d1; S->dv[t * 3 + 2] = d2;
            float dot = d0 * d0 + d1 * d1 + d2 * d2 + 1e-20f;
            S->l2[t] = valid ? dot : 0.f;
            S->len[t] = sqrtf(dot);
        }
        __syncthreads();
        {                                                // stage 2: act0 -> X
            int e = t >> 1, kh = t & 1;
            int s = S->sidx[e];
            float l2v = S->l2[e];
            const float* hsr = g_hs + s * FD + kh * 64;
#pragma unroll 8
            for (int j = 0; j < 64; j += 2) {
                int c = kh * 64 + j;
                float v0 = siluf(l2v * S->w0[c]     + hsr[j]     + S->hrb[c]);
                float v1 = siluf(l2v * S->w0[c + 1] + hsr[j + 1] + S->hrb[c + 1]);
                st_split2(S->xhi, S->xlo, img_off(e, c), v0, v1);
            }
        }
        CP_WAIT0();
        __syncthreads();

        // G1: Y = silu(X @ We1 + be1)
        gemm_tc<true, false, true>(S, S->xhi, S->xlo, wb + 1 * 32768,
                                   S->bb1, 0, S->yhi, S->ylo, t);
        CP_WAIT0(); __syncthreads();

        // G2: m = Y @ We2 + be2 -> X; dot winf
        gemm_tc<false, true, true>(S, S->yhi, S->ylo, wb + 2 * 32768,
                                   S->bb2, S->winf, S->xhi, S->xlo, t);
        CP_WAIT0(); __syncthreads();
        if (t < TILE) {
            bool valid = (tile * TILE + t) < EPN;
            S->gate[t] = valid ? sigmf(binf_s + S->gpart[t] + S->gpart[TILE + t]) : 0.f;
        }
        __syncthreads();
        {                                                // magg partial from X (m)
            float acc = 0.f;
#pragma unroll 4
            for (int e = hh * 64; e < hh * 64 + 64; e++) {
                int adr = img_off(e, kk);
                float m = __bfloat162float(*reinterpret_cast<__nv_bfloat16*>(S->xhi + adr))
                        + __bfloat162float(*reinterpret_cast<__nv_bfloat16*>(S->xlo + adr));
                acc += m * S->gate[e];
            }
            mreg += acc;
        }

        // G3: Y = silu(X @ Wx0 + bx0)
        gemm_tc<true, false, true>(S, S->xhi, S->xlo, wb + 3 * 32768,
                                   S->bbx0, 0, S->yhi, S->ylo, t);
        CP_WAIT0(); __syncthreads();

        // G4: px partial = silu(Y @ Wx1 + bx1) . wxo  (no store)
        gemm_tc<true, true, false>(S, S->yhi, S->ylo, wb,
                                   S->bbx1, S->wxo, S->yhi, S->ylo, t);
        __syncthreads();
        if (t < TILE)
            S->pxs[t] = (bxo_s + S->gpart[t] + S->gpart[TILE + t]) / (1.f + S->len[t]);
        __syncthreads();
        if (t < TILE) {                                  // vac partial
            float p = S->pxs[t];
            S->vred[t] = p * S->dv[t * 3];
            S->vred[TILE + t] = p * S->dv[t * 3 + 1];
            S->vred[2 * TILE + t] = p * S->dv[t * 3 + 2];
        }
        __syncthreads();
        if (t < 96) {
            int c = t >> 5, l = t & 31;
            const float* vr = S->vred + c * TILE;
            float v = (vr[l] + vr[l + 32]) + (vr[l + 64] + vr[l + 96]);
#pragma unroll
            for (int o = 16; o; o >>= 1) v += __shfl_down_sync(0xffffffffu, v, o);
            if (l == 0) S->vaccs[c] += v;
        }
        __syncthreads();
    }

    S->maggs[t] = mreg;
    __syncthreads();
    if (t < FD)
        g_magg[i * FD + t] = (S->maggs[t] + S->maggs[FD + t]) * rsqrtf(511.f);
    if (t < 3) g_vac[i * 3 + t] = S->vaccs[t] * (1.f / 511.f);
}

// weights -> T[n][k] bf16 hi/lo swizzled images (one CTA per matrix)
__global__ void __launch_bounds__(256) kwprep(
    const float* __restrict__ We1, const float* __restrict__ We2,
    const float* __restrict__ Wx0, const float* __restrict__ Wx1)
{
    int m = blockIdx.x, b = m >> 2, g = m & 3;
    const float* W = (g == 0 ? We1 : g == 1 ? We2 : g == 2 ? Wx0 : Wx1) + b * FD * FD;
    char* blob = reinterpret_cast<char*>(g_wb + m * 32768);
    int t = threadIdx.x, n = t & 127, kh = t >> 7;
    for (int kc = 0; kc < 8; kc++) {
        int kchunk = kh * 8 + kc;
        unsigned qh[4], ql[4];
#pragma unroll
        for (int u = 0; u < 4; u++) {
            int k = kchunk * 8 + u * 2;
            float x0 = W[k * FD + n], x1 = W[(k + 1) * FD + n];
            __nv_bfloat16 h0 = __float2bfloat16(x0), h1 = __float2bfloat16(x1);
            __nv_bfloat16 l0 = __float2bfloat16(x0 - __bfloat162float(h0));
            __nv_bfloat16 l1 = __float2bfloat16(x1 - __bfloat162float(h1));
            qh[u] = (unsigned)__bfloat16_as_ushort(h0) | ((unsigned)__bfloat16_as_ushort(h1) << 16);
            ql[u] = (unsigned)__bfloat16_as_ushort(l0) | ((unsigned)__bfloat16_as_ushort(l1) << 16);
        }
        int off = (n << 8) + ((kchunk ^ (n & 7)) << 4);
        *reinterpret_cast<uint4*>(blob + off)         = make_uint4(qh[0], qh[1], qh[2], qh[3]);
        *reinterpret_cast<uint4*>(blob + 32768 + off) = make_uint4(ql[0], ql[1], ql[2], ql[3]);
    }
}

__global__ void ksetup(const float* __restrict__ x)
{
    __shared__ float r0[256], r1[256], r2[256];
    __shared__ float mean[3];
    int t = threadIdx.x;
    float s0 = 0.f, s1 = 0.f, s2 = 0.f;
    for (int n = t; n < NN; n += 256) {
        s0 += x[n * 3]; s1 += x[n * 3 + 1]; s2 += x[n * 3 + 2];
    }
    r0[t] = s0; r1[t] = s1; r2[t] = s2;
    __syncthreads();
    for (int s = 128; s > 0; s >>= 1) {
        if (t < s) { r0[t] += r0[t + s]; r1[t] += r1[t + s]; r2[t] += r2[t + s]; }
        __syncthreads();
    }
    if (t == 0) { mean[0] = r0[0] / NN; mean[1] = r1[0] / NN; mean[2] = r2[0] / NN; }
    __syncthreads();
    for (int n = t; n < NN; n += 256)
#pragma unroll
        for (int c = 0; c < 3; c++) {
            float v = x[n * 3 + c] - mean[c];
            g_vec[n * 3 + c] = v; g_vec0[n * 3 + c] = v;
        }
}

__global__ void knode0(const float* __restrict__ h,
                       const float* __restrict__ Wh0, const float* __restrict__ bh0,
                       const float* __restrict__ We0, const float* __restrict__ be0)
{
    __shared__ float hrow[16];
    __shared__ float hfs[FD];
    int i = blockIdx.x, c = threadIdx.x;
    if (c < 16) hrow[c] = h[i * 16 + c];
    __syncthreads();
    float acc = bh0[c];
#pragma unroll
    for (int k = 0; k < 16; k++) acc += hrow[k] * Wh0[k * FD + c];
    g_hf[i * FD + c] = acc;
    hfs[c] = acc;
    __syncthreads();
    float s1 = 0.f, s2 = be0[c];
#pragma unroll 8
    for (int k = 0; k < FD; k++) {
        float hv = hfs[k];
        s1 += hv * We0[(1 + k) * FD + c];
        s2 += hv * We0[(129 + k) * FD + c];
    }
    g_hs[i * FD + c] = s1;
    g_hr[i * FD + c] = s2;
}

__global__ void knode(const float* __restrict__ Wp0, const float* __restrict__ bp0,
                      const float* __restrict__ Wp1, const float* __restrict__ bp1,
                      const float* __restrict__ Wpl, const float* __restrict__ bpl,
                      const float* __restrict__ We0n, const float* __restrict__ be0n,
                      int doNext)
{
    __shared__ float in0[2 * FD], t0s[FD], t1s[FD];
    int i = blockIdx.x, c = threadIdx.x;
    if (c < 3) g_vec[i * 3 + c] += g_vac[i * 3 + c];
    in0[c] = g_magg[i * FD + c];
    float hf = g_hf[i * FD + c];
    in0[FD + c] = hf;
    __syncthreads();
    float a = bp0[c];
#pragma unroll 8
    for (int k = 0; k < 2 * FD; k++) a += in0[k] * Wp0[k * FD + c];
    t0s[c] = siluf(a);
    __syncthreads();
    float b = bp1[c];
#pragma unroll 8
    for (int k = 0; k < FD; k++) b += t0s[k] * Wp1[k * FD + c];
    t1s[c] = b;
    __syncthreads();
    float d = bpl[c];
#pragma unroll 8
    for (int k = 0; k < FD; k++) d += t1s[k] * Wpl[k * FD + c];
    float nhf = hf + d;
    g_hf[i * FD + c] = nhf;
    if (doNext) {
        t0s[c] = nhf;
        __syncthreads();
        float s1 = 0.f, s2 = be0n[c];
#pragma unroll 8
        for (int k = 0; k < FD; k++) {
            float hv = t0s[k];
            s1 += hv * We0n[(1 + k) * FD + c];
            s2 += hv * We0n[(129 + k) * FD + c];
        }
        g_hs[i * FD + c] = s1;
        g_hr[i * FD + c] = s2;
    }
}

__global__ void kout(const float* __restrict__ Wv,
                     const float* __restrict__ Wr, const float* __restrict__ br,
                     float* __restrict__ out)
{
    __shared__ float red[FD], p[FD];
    int i = blockIdx.x, c = threadIdx.x;
    float hf = g_hf[i * FD + c];
    red[c] = hf;
    __syncthreads();
    for (int s = 64; s > 0; s >>= 1) {
        if (c < s) red[c] = fmaxf(red[c], red[c + s]);
        __syncthreads();
    }
    float mx = red[0];
    __syncthreads();
    float ex = __expf(hf - mx);
    red[c] = ex;
    __syncthreads();
    for (int s = 64; s > 0; s >>= 1) {
        if (c < s) red[c] += red[c + s];
        __syncthreads();
    }
    float inv = 1.f / red[0];
    __syncthreads();
    p[c] = ex * inv;
    __syncthreads();
    if (c < 32) {
        float a = br[c];
#pragma unroll 8
        for (int k = 0; k < FD; k++) a += p[k] * Wr[k * 32 + c];
        out[NN * 6 + i * 32 + c] = a;
    }
    if (c < 6) {
        int o = c / 3, cc = c % 3;
        out[i * 6 + c] = (g_vec[i * 3 + cc] - g_vec0[i * 3 + cc]) * Wv[o];
    }
}

extern "C" void kernel_launch(void* const* d_in, const int* in_sizes, int n_in,
                              void* d_out, int out_size)
{
    const float* x   = (const float*)d_in[0];
    const float* h   = (const float*)d_in[1];
    const int* snd   = (const int*)  d_in[2];
    const float* Wh0 = (const float*)d_in[4];
    const float* bh0 = (const float*)d_in[5];
    const float* We0 = (const float*)d_in[6];
    const float* be0 = (const float*)d_in[7];
    const float* We1 = (const float*)d_in[8];
    const float* be1 = (const float*)d_in[9];
    const float* We2 = (const float*)d_in[10];
    const float* be2 = (const float*)d_in[11];
    const float* Winf= (const float*)d_in[12];
    const float* binf= (const float*)d_in[13];
    const float* Wx0 = (const float*)d_in[14];
    const float* bx0 = (const float*)d_in[15];
    const float* Wx1 = (const float*)d_in[16];
    const float* bx1 = (const float*)d_in[17];
    const float* Wxo = (const float*)d_in[18];
    const float* bxo = (const float*)d_in[19];
    const float* Wp0 = (const float*)d_in[20];
    const float* bp0 = (const float*)d_in[21];
    const float* Wp1 = (const float*)d_in[22];
    const float* bp1 = (const float*)d_in[23];
    const float* Wpl = (const float*)d_in[24];
    const float* bpl = (const float*)d_in[25];
    const float* Wv  = (const float*)d_in[26];
    const float* Wr  = (const float*)d_in[27];
    const float* br  = (const float*)d_in[28];
    float* out = (float*)d_out;

    int smem = (int)sizeof(ES);
    cudaFuncSetAttribute(kedge, cudaFuncAttributeMaxDynamicSharedMemorySize, smem);

    const int WB = FD * FD, W0B = 257 * FD, WP0 = 2 * FD * FD;

    ksetup<<<1, 256>>>(x);
    knode0<<<NN, FD>>>(h, Wh0, bh0, We0, be0);
    kwprep<<<8, 256>>>(We1, We2, Wx0, Wx1);

    for (int b = 0; b < 2; b++) {
        kedge<<<NN, 256, smem>>>(snd, We0 + b * W0B,
            be1 + b * FD, be2 + b * FD, Winf + b * FD, binf + b,
            bx0 + b * FD, bx1 + b * FD, Wxo + b * FD, bxo + b, b);
        knode<<<NN, FD>>>(Wp0 + b * WP0, bp0 + b * FD,
                          Wp1 + b * WB, bp1 + b * FD,
                          Wpl + b * WB, bpl + b * FD,
                          We0 + W0B, be0 + FD, b == 0 ? 1 : 0);
    }
    kout<<<NN, FD>>>(Wv, Wr, br, out);
}